// round 1
// baseline (speedup 1.0000x reference)
#include <cuda_runtime.h>
#include <cuda_bf16.h>

// out[b,e] = sparsity[b,e] * sum_h ( sum_m hidden[b,m,h] ) * ( sum_n weight[e,h,n] )
// A=1, B=32, M=32, H=1024, E=8, N=1024
//
// d_in[0] = hidden  (1*32*32*1024 f32)
// d_in[1] = sparsity (1*32*1*8   f32)
// d_in[2] = weight  (1*8*1024*1024 f32)
// d_out   = 1*32*8 f32

#define Bn 32
#define Mn 32
#define Hn 1024
#define En 8
#define Nn 1024

// Scratch (no cudaMalloc allowed)
__device__ float g_ws[En * Hn];    // ws[e*H + h] = sum_n weight[e,h,n]
__device__ float g_hs[Bn * Hn];    // hs[b*H + h] = sum_m hidden[b,m,h]

// Phase 1: reductions.
// Blocks [0, 1024): weight rows. 8 warps/block, one warp per (e,h) row of 1024 floats.
// Blocks [1024, 1056): hidden. One block per b; threads stride over h, loop over m.
__global__ void __launch_bounds__(256) reduce_kernel(
    const float* __restrict__ hidden,
    const float* __restrict__ weight)
{
    const int tid  = threadIdx.x;
    const int lane = tid & 31;
    const int wid  = tid >> 5;

    if (blockIdx.x < (En * Hn) / 8) {
        // ---- weight reduction: row r = blockIdx.x*8 + wid, 1024 floats ----
        const int r = blockIdx.x * 8 + wid;   // r in [0, 8192) = e*H + h
        const float4* row = reinterpret_cast<const float4*>(weight + (size_t)r * Nn);
        float s = 0.f;
        #pragma unroll
        for (int k = 0; k < Nn / 4 / 32; k++) {   // 8 float4 per lane
            float4 v = row[lane + k * 32];
            s += (v.x + v.y) + (v.z + v.w);
        }
        // warp reduce
        #pragma unroll
        for (int off = 16; off > 0; off >>= 1)
            s += __shfl_xor_sync(0xffffffffu, s, off);
        if (lane == 0) g_ws[r] = s;
    } else {
        // ---- hidden reduction: one block per b ----
        const int b = blockIdx.x - (En * Hn) / 8;   // [0, 32)
        const float* base = hidden + (size_t)b * Mn * Hn;
        #pragma unroll
        for (int h = tid; h < Hn; h += 256) {
            float s = 0.f;
            #pragma unroll
            for (int m = 0; m < Mn; m++)
                s += base[m * Hn + h];
            g_hs[b * Hn + h] = s;
        }
    }
}

// Phase 2: out[b,e] = sparsity[b*8+e] * dot(hs[b,:], ws[e,:])  (K=1024)
// One block per output element; 128 threads, shared-memory tree reduce.
__global__ void __launch_bounds__(128) dot_kernel(
    const float* __restrict__ sparsity,
    float* __restrict__ out)
{
    const int idx = blockIdx.x;          // [0, 256)
    const int b = idx >> 3;
    const int e = idx & 7;
    const int tid = threadIdx.x;

    const float4* hs = reinterpret_cast<const float4*>(g_hs + b * Hn);
    const float4* ws = reinterpret_cast<const float4*>(g_ws + e * Hn);

    float s = 0.f;
    #pragma unroll
    for (int k = tid; k < Hn / 4; k += 128) {  // 2 float4 per thread
        float4 a = hs[k];
        float4 w = ws[k];
        s += a.x * w.x + a.y * w.y + a.z * w.z + a.w * w.w;
    }
    // warp reduce
    #pragma unroll
    for (int off = 16; off > 0; off >>= 1)
        s += __shfl_xor_sync(0xffffffffu, s, off);

    __shared__ float warp_sums[4];
    if ((tid & 31) == 0) warp_sums[tid >> 5] = s;
    __syncthreads();
    if (tid == 0) {
        float t = warp_sums[0] + warp_sums[1] + warp_sums[2] + warp_sums[3];
        out[idx] = t * sparsity[idx];
    }
}

extern "C" void kernel_launch(void* const* d_in, const int* in_sizes, int n_in,
                              void* d_out, int out_size)
{
    const float* hidden   = (const float*)d_in[0];
    const float* sparsity = (const float*)d_in[1];
    const float* weight   = (const float*)d_in[2];
    float* out = (float*)d_out;

    // 1024 weight-blocks + 32 hidden-blocks
    reduce_kernel<<<(En * Hn) / 8 + Bn, 256>>>(hidden, weight);
    dot_kernel<<<Bn * En, 128>>>(sparsity, out);
}